// round 3
// baseline (speedup 1.0000x reference)
#include <cuda_runtime.h>
#include <cstdint>

// GeneralAttention: B=2,H=16,S=2048,D=64 fp32, mask [B,1,S,S] int32 (0 -> fill -32768)
// Flash-attention, fp32 via packed fma.rn.f32x2 (2x FFMA throughput on sm_103a).

#define Bc 2
#define Hc 16
#define Sc 2048
#define Dc 64
#define BR 128
#define BKT 128
#define NT 256

// smem layout (floats):
//   Qs  [64][128]           @ 0        (8192)   Q transposed, d-major
//   Ks2 [128][132]          @ 8192     (16896)  K duplicated pairs (k,k) along d  -- aliased by Ps after QK
//   Vs2 [128][128]          @ 25088    (16384)  V duplicated pairs (v,v) along d
#define QS_OFF   0
#define KS_OFF   8192
#define PS_OFF   8192          /* Ps aliases Ks2, stride 132 */
#define VS_OFF   25088
#define SMEM_FLOATS (8192 + 16896 + 16384)
#define SMEM_BYTES (SMEM_FLOATS * 4)

#define LOG2E 1.4426950408889634f

using u64 = unsigned long long;

__device__ __forceinline__ u64 ffma2(u64 a, u64 b, u64 c) {
    u64 d;
    asm("fma.rn.f32x2 %0, %1, %2, %3;" : "=l"(d) : "l"(a), "l"(b), "l"(c));
    return d;
}
__device__ __forceinline__ u64 fmul2(u64 a, u64 b) {
    u64 d;
    asm("mul.rn.f32x2 %0, %1, %2;" : "=l"(d) : "l"(a), "l"(b));
    return d;
}
__device__ __forceinline__ u64 pk2(float lo, float hi) {
    u64 r;
    asm("mov.b64 %0, {%1, %2};" : "=l"(r) : "f"(lo), "f"(hi));
    return r;
}
__device__ __forceinline__ void unpk(u64 v, float& lo, float& hi) {
    asm("mov.b64 {%0, %1}, %2;" : "=f"(lo), "=f"(hi) : "l"(v));
}
__device__ __forceinline__ float ex2(float x) {
    float r;
    asm("ex2.approx.ftz.f32 %0, %1;" : "=f"(r) : "f"(x));
    return r;
}

__global__ void __launch_bounds__(NT, 1)
attn_kernel(const float* __restrict__ Q, const float* __restrict__ K,
            const float* __restrict__ V, const int* __restrict__ Mask,
            float* __restrict__ Out)
{
    extern __shared__ float sm[];
    float* Qs  = sm + QS_OFF;   // [64][128]
    float* Ks2 = sm + KS_OFF;   // [128][132]
    float* Ps  = sm + PS_OFF;   // [128][132] (alias of Ks2)
    float* Vs2 = sm + VS_OFF;   // [128][128]

    const int tid = threadIdx.x;
    const int tx = tid & 15;        // 0..15
    const int ty = tid >> 4;        // 0..15
    const int ty8 = ty * 8;
    const int qt = blockIdx.x;      // q tile
    const int bh = blockIdx.y;      // b*H + h
    const int b  = bh >> 4;         // H = 16
    const int q0 = qt * BR;

    const float* Qg = Q + ((size_t)bh * Sc + q0) * Dc;
    const float* Kg = K + (size_t)bh * Sc * Dc;
    const float* Vg = V + (size_t)bh * Sc * Dc;
    const int*   Mg = Mask + (size_t)b * Sc * Sc + (size_t)q0 * Sc;
    float*       Og = Out + ((size_t)bh * Sc + q0) * Dc;

    // ---- load Q tile transposed: Qs[d][r] (one-time) ----
    #pragma unroll
    for (int it = 0; it < 8; ++it) {
        int i  = tid + NT * it;        // float4 index over [128][16]
        int r  = i >> 4;
        int d4 = i & 15;
        float4 v = ((const float4*)Qg)[i];
        Qs[(d4 * 4 + 0) * 128 + r] = v.x;
        Qs[(d4 * 4 + 1) * 128 + r] = v.y;
        Qs[(d4 * 4 + 2) * 128 + r] = v.z;
        Qs[(d4 * 4 + 3) * 128 + r] = v.w;
    }

    float m_i[8], l_i[8];
    #pragma unroll
    for (int i = 0; i < 8; ++i) { m_i[i] = -1e30f; l_i[i] = 0.0f; }

    u64 O2[4][4];   // row-pairs (2p,2p+1) x cols (4*tx + c)
    #pragma unroll
    for (int p = 0; p < 4; ++p)
        #pragma unroll
        for (int c = 0; c < 4; ++c) O2[p][c] = 0ull;

    for (int kt = 0; kt < Sc / BKT; ++kt) {
        __syncthreads();   // previous PV reads of Ps/Vs2 done

        // ---- load K,V tiles with value duplication ----
        const float4* Kt = (const float4*)(Kg + (size_t)kt * BKT * Dc);
        const float4* Vt = (const float4*)(Vg + (size_t)kt * BKT * Dc);
        #pragma unroll
        for (int it = 0; it < 8; ++it) {
            int i  = tid + NT * it;
            int rr = i >> 4;
            int d4 = i & 15;
            float4 kv = Kt[i];
            float2* kd = (float2*)&Ks2[rr * 132 + d4 * 8];
            kd[0] = make_float2(kv.x, kv.x);
            kd[1] = make_float2(kv.y, kv.y);
            kd[2] = make_float2(kv.z, kv.z);
            kd[3] = make_float2(kv.w, kv.w);
            float4 vv = Vt[i];
            float2* vd = (float2*)&Vs2[rr * 128 + d4 * 8];
            vd[0] = make_float2(vv.x, vv.x);
            vd[1] = make_float2(vv.y, vv.y);
            vd[2] = make_float2(vv.z, vv.z);
            vd[3] = make_float2(vv.w, vv.w);
        }
        __syncthreads();

        // ---- S = Q K^T  (rows ty8..ty8+7, cols tx+16j) ----
        u64 acc2[4][8];
        #pragma unroll
        for (int p = 0; p < 4; ++p)
            #pragma unroll
            for (int j = 0; j < 8; ++j) acc2[p][j] = 0ull;

        #pragma unroll 2
        for (int d2 = 0; d2 < 32; ++d2) {
            const float* qp = &Qs[(2 * d2) * 128 + ty8];
            ulonglong2 qa0 = *(const ulonglong2*)(qp);
            ulonglong2 qb0 = *(const ulonglong2*)(qp + 4);
            ulonglong2 qa1 = *(const ulonglong2*)(qp + 128);
            ulonglong2 qb1 = *(const ulonglong2*)(qp + 132);
            #pragma unroll
            for (int j = 0; j < 8; ++j) {
                ulonglong2 kv = *(const ulonglong2*)&Ks2[(tx + 16 * j) * 132 + 4 * d2];
                acc2[0][j] = ffma2(qa0.x, kv.x, acc2[0][j]);
                acc2[1][j] = ffma2(qa0.y, kv.x, acc2[1][j]);
                acc2[2][j] = ffma2(qb0.x, kv.x, acc2[2][j]);
                acc2[3][j] = ffma2(qb0.y, kv.x, acc2[3][j]);
                acc2[0][j] = ffma2(qa1.x, kv.y, acc2[0][j]);
                acc2[1][j] = ffma2(qa1.y, kv.y, acc2[1][j]);
                acc2[2][j] = ffma2(qb1.x, kv.y, acc2[2][j]);
                acc2[3][j] = ffma2(qb1.y, kv.y, acc2[3][j]);
            }
        }

        // ---- unpack scores ----
        float sv[8][8];
        #pragma unroll
        for (int p = 0; p < 4; ++p)
            #pragma unroll
            for (int j = 0; j < 8; ++j)
                unpk(acc2[p][j], sv[2 * p][j], sv[2 * p + 1][j]);

        // ---- mask + online softmax ----
        float alpha_r[8];
        #pragma unroll
        for (int i = 0; i < 8; ++i) {
            const int* mrow = Mg + (size_t)(ty8 + i) * Sc + kt * BKT + tx;
            int mk[8];
            #pragma unroll
            for (int j = 0; j < 8; ++j) mk[j] = mrow[16 * j];

            float mx = -1e30f;
            #pragma unroll
            for (int j = 0; j < 8; ++j) {
                float s = (mk[j] == 0) ? -32768.0f : sv[i][j] * 0.125f;
                sv[i][j] = s;
                mx = fmaxf(mx, s);
            }
            mx = fmaxf(mx, __shfl_xor_sync(0xffffffffu, mx, 1));
            mx = fmaxf(mx, __shfl_xor_sync(0xffffffffu, mx, 2));
            mx = fmaxf(mx, __shfl_xor_sync(0xffffffffu, mx, 4));
            mx = fmaxf(mx, __shfl_xor_sync(0xffffffffu, mx, 8));

            float mnew = fmaxf(m_i[i], mx);
            alpha_r[i] = ex2((m_i[i] - mnew) * LOG2E);
            m_i[i] = mnew;

            float rs = 0.0f;
            #pragma unroll
            for (int j = 0; j < 8; ++j) {
                float p = ex2((sv[i][j] - mnew) * LOG2E);
                sv[i][j] = p;
                rs += p;
            }
            rs += __shfl_xor_sync(0xffffffffu, rs, 1);
            rs += __shfl_xor_sync(0xffffffffu, rs, 2);
            rs += __shfl_xor_sync(0xffffffffu, rs, 4);
            rs += __shfl_xor_sync(0xffffffffu, rs, 8);
            l_i[i] = l_i[i] * alpha_r[i] + rs;
        }

        // ---- rescale O ----
        #pragma unroll
        for (int p = 0; p < 4; ++p) {
            u64 a2 = pk2(alpha_r[2 * p], alpha_r[2 * p + 1]);
            #pragma unroll
            for (int c = 0; c < 4; ++c) O2[p][c] = fmul2(O2[p][c], a2);
        }

        __syncthreads();   // all QK reads of Ks2 done before overwriting with Ps

        // ---- store P transposed: Ps[k][r] ----
        #pragma unroll
        for (int j = 0; j < 8; ++j) {
            float* pdst = &Ps[(tx + 16 * j) * 132 + ty8];
            #pragma unroll
            for (int i = 0; i < 8; ++i) pdst[i] = sv[i][j];
        }
        __syncthreads();

        // ---- O += P @ V ----
        #pragma unroll 4
        for (int k = 0; k < BKT; ++k) {
            const float* pp = &Ps[k * 132 + ty8];
            ulonglong2 pa = *(const ulonglong2*)(pp);
            ulonglong2 pb = *(const ulonglong2*)(pp + 4);
            const float* vp = &Vs2[k * 128 + tx * 8];
            ulonglong2 va = *(const ulonglong2*)(vp);
            ulonglong2 vb = *(const ulonglong2*)(vp + 4);
            O2[0][0] = ffma2(pa.x, va.x, O2[0][0]);
            O2[0][1] = ffma2(pa.x, va.y, O2[0][1]);
            O2[0][2] = ffma2(pa.x, vb.x, O2[0][2]);
            O2[0][3] = ffma2(pa.x, vb.y, O2[0][3]);
            O2[1][0] = ffma2(pa.y, va.x, O2[1][0]);
            O2[1][1] = ffma2(pa.y, va.y, O2[1][1]);
            O2[1][2] = ffma2(pa.y, vb.x, O2[1][2]);
            O2[1][3] = ffma2(pa.y, vb.y, O2[1][3]);
            O2[2][0] = ffma2(pb.x, va.x, O2[2][0]);
            O2[2][1] = ffma2(pb.x, va.y, O2[2][1]);
            O2[2][2] = ffma2(pb.x, vb.x, O2[2][2]);
            O2[2][3] = ffma2(pb.x, vb.y, O2[2][3]);
            O2[3][0] = ffma2(pb.y, va.x, O2[3][0]);
            O2[3][1] = ffma2(pb.y, va.y, O2[3][1]);
            O2[3][2] = ffma2(pb.y, vb.x, O2[3][2]);
            O2[3][3] = ffma2(pb.y, vb.y, O2[3][3]);
        }
    }

    // ---- epilogue: normalize + write ----
    float invl[8];
    #pragma unroll
    for (int i = 0; i < 8; ++i) invl[i] = 1.0f / l_i[i];

    #pragma unroll
    for (int p = 0; p < 4; ++p) {
        float lo0, hi0, lo1, hi1, lo2, hi2, lo3, hi3;
        unpk(O2[p][0], lo0, hi0);
        unpk(O2[p][1], lo1, hi1);
        unpk(O2[p][2], lo2, hi2);
        unpk(O2[p][3], lo3, hi3);
        int r0 = ty8 + 2 * p;
        float4 o_lo = make_float4(lo0 * invl[2 * p], lo1 * invl[2 * p],
                                  lo2 * invl[2 * p], lo3 * invl[2 * p]);
        float4 o_hi = make_float4(hi0 * invl[2 * p + 1], hi1 * invl[2 * p + 1],
                                  hi2 * invl[2 * p + 1], hi3 * invl[2 * p + 1]);
        ((float4*)(Og + (size_t)r0 * Dc))[tx] = o_lo;
        ((float4*)(Og + (size_t)(r0 + 1) * Dc))[tx] = o_hi;
    }
}

extern "C" void kernel_launch(void* const* d_in, const int* in_sizes, int n_in,
                              void* d_out, int out_size)
{
    const float* Q    = (const float*)d_in[0];
    const float* K    = (const float*)d_in[1];
    const float* V    = (const float*)d_in[2];
    const int*   mask = (const int*)d_in[3];
    float* out = (float*)d_out;

    cudaFuncSetAttribute(attn_kernel, cudaFuncAttributeMaxDynamicSharedMemorySize, SMEM_BYTES);
    dim3 grid(Sc / BR, Bc * Hc);
    attn_kernel<<<grid, NT, SMEM_BYTES>>>(Q, K, V, mask, out);
}

// round 5
// speedup vs baseline: 3.4267x; 3.4267x over previous
#include <cuda_runtime.h>
#include <cstdint>

using u32 = unsigned int;

#define Sc 2048
#define NT 256
#define NTILES 16
#define LOG2E 1.4426950408889634f

// smem: six bf16 tiles [128 rows][64 cols], 128B/row, SW128 swizzle
#define QH_OFF 0
#define QL_OFF 16384
#define KH_OFF 32768
#define KL_OFF 49152
#define VH_OFF 65536
#define VL_OFF 81920
#define SMEM_BYTES 98304

__device__ __forceinline__ u32 swz(u32 x) { return x ^ ((x >> 3) & 0x70); }
__device__ __forceinline__ u32 smem_u32(const void* p) {
    u32 a;
    asm("{ .reg .u64 t; cvta.to.shared.u64 t, %1; cvt.u32.u64 %0, t; }" : "=r"(a) : "l"(p));
    return a;
}
__device__ __forceinline__ u32 packbf2(float lo, float hi) {   // lo -> low half
    u32 d; asm("cvt.rn.bf16x2.f32 %0, %1, %2;" : "=r"(d) : "f"(hi), "f"(lo)); return d;
}
__device__ __forceinline__ float bf_lo(u32 p) { return __uint_as_float(p << 16); }
__device__ __forceinline__ float bf_hi(u32 p) { return __uint_as_float(p & 0xffff0000u); }
__device__ __forceinline__ void split2(float a, float b, u32& h, u32& l) {
    h = packbf2(a, b);
    l = packbf2(a - bf_lo(h), b - bf_hi(h));
}

// 2^y on the FMA pipe (no MUFU). y <= 0 expected; clamped at -126.
__device__ __forceinline__ float exp2p(float y) {
    y = fmaxf(y, -126.0f);
    float r = y + 12582912.0f;           // 1.5*2^23 round-to-int magic
    int   n = __float_as_int(r);
    float f = y - (r - 12582912.0f);     // f in [-0.5, 0.5]
    float p = 0.0013333558f;
    p = fmaf(p, f, 0.0096181291f);
    p = fmaf(p, f, 0.0555041087f);
    p = fmaf(p, f, 0.2402265070f);
    p = fmaf(p, f, 0.6931471806f);
    p = fmaf(p, f, 1.0f);
    return __int_as_float(__float_as_int(p) + (n << 23));
}

__device__ __forceinline__ void ldsm4(u32& r0, u32& r1, u32& r2, u32& r3, u32 a) {
    asm volatile("ldmatrix.sync.aligned.m8n8.x4.shared.b16 {%0,%1,%2,%3}, [%4];"
                 : "=r"(r0), "=r"(r1), "=r"(r2), "=r"(r3) : "r"(a));
}
__device__ __forceinline__ void ldsm4t(u32& r0, u32& r1, u32& r2, u32& r3, u32 a) {
    asm volatile("ldmatrix.sync.aligned.m8n8.x4.trans.shared.b16 {%0,%1,%2,%3}, [%4];"
                 : "=r"(r0), "=r"(r1), "=r"(r2), "=r"(r3) : "r"(a));
}
__device__ __forceinline__ void mma_bf16(float* d, u32 a0, u32 a1, u32 a2, u32 a3, u32 b0, u32 b1) {
    asm volatile("mma.sync.aligned.m16n8k16.row.col.f32.bf16.bf16.f32 "
                 "{%0,%1,%2,%3}, {%4,%5,%6,%7}, {%8,%9}, {%0,%1,%2,%3};"
                 : "+f"(d[0]), "+f"(d[1]), "+f"(d[2]), "+f"(d[3])
                 : "r"(a0), "r"(a1), "r"(a2), "r"(a3), "r"(b0), "r"(b1));
}

__global__ void __launch_bounds__(NT, 1)
attn_mma(const float* __restrict__ Q, const float* __restrict__ K,
         const float* __restrict__ V, const int* __restrict__ Mask,
         float* __restrict__ Out)
{
    extern __shared__ char smc[];
    const u32 sb = smem_u32(smc);
    const int tid  = threadIdx.x;
    const int wid  = tid >> 5;
    const int lane = tid & 31;
    const int gid  = lane >> 2;   // group-of-4 id = row within 8
    const int tig  = lane & 3;

    const int bh = blockIdx.y;
    const int b  = bh >> 4;
    const int q0 = blockIdx.x * 128;

    const float* Qg = Q + ((size_t)bh * Sc + q0) * 64;
    const float* Kg = K + (size_t)bh * Sc * 64;
    const float* Vg = V + (size_t)bh * Sc * 64;
    const int*   Mg = Mask + (size_t)b * Sc * Sc + (size_t)q0 * Sc;
    float*       Og = Out + ((size_t)bh * Sc + q0) * 64;

    // ---- Q -> smem bf16 splits (once) ----
    #pragma unroll
    for (int it = 0; it < 8; ++it) {
        int i = tid + NT * it;               // float4 over [128][16]
        int r = i >> 4, c4 = i & 15;
        float4 v = ((const float4*)Qg)[i];
        u32 off = swz((u32)(r * 128 + c4 * 8));
        u32 h0, l0, h1, l1;
        split2(v.x, v.y, h0, l0);
        split2(v.z, v.w, h1, l1);
        *(uint2*)(smc + QH_OFF + off) = make_uint2(h0, h1);
        *(uint2*)(smc + QL_OFF + off) = make_uint2(l0, l1);
    }

    // ldmatrix per-lane address components
    const u32 aRB  = (u32)(16 * wid + (lane & 7) + ((lane >> 3) & 1) * 8) * 128; // A row bytes
    const u32 aKH  = (u32)(lane >> 4) * 16;                                      // A k-half bytes
    const int bRow = (((lane >> 4) & 1) << 3) + (lane & 7);                      // K B row within npair
    const u32 bKH  = (u32)((lane >> 3) & 1) * 16;                                // K B k-half bytes
    const int vRow = (((lane >> 3) & 1) << 3) + (lane & 7);                      // V row within ktile
    const u32 vDB  = (u32)(lane >> 4) * 16;                                      // V d-half bytes

    const int row0 = 16 * wid + gid;
    const int row1 = row0 + 8;
    const int* M0 = Mg + (size_t)row0 * Sc;
    const int* M1 = Mg + (size_t)row1 * Sc;

    float O[8][4];
    #pragma unroll
    for (int n = 0; n < 8; ++n)
        #pragma unroll
        for (int c = 0; c < 4; ++c) O[n][c] = 0.0f;
    float m0 = -1e30f, m1 = -1e30f, l0 = 0.0f, l1 = 0.0f;

    for (int kt = 0; kt < NTILES; ++kt) {
        // ---- K tile: gmem -> regs -> (sync) -> smem splits ----
        const float4* Kt = (const float4*)(Kg + (size_t)kt * 128 * 64);
        const float4* Vt = (const float4*)(Vg + (size_t)kt * 128 * 64);
        float4 stg[8];
        #pragma unroll
        for (int it = 0; it < 8; ++it) stg[it] = Kt[tid + NT * it];
        __syncthreads();                       // prior iter's ldmatrix reads done
        #pragma unroll
        for (int it = 0; it < 8; ++it) {
            int i = tid + NT * it;
            int r = i >> 4, c4 = i & 15;
            u32 off = swz((u32)(r * 128 + c4 * 8));
            u32 h0, lo0, h1, lo1;
            split2(stg[it].x, stg[it].y, h0, lo0);
            split2(stg[it].z, stg[it].w, h1, lo1);
            *(uint2*)(smc + KH_OFF + off) = make_uint2(h0, h1);
            *(uint2*)(smc + KL_OFF + off) = make_uint2(lo0, lo1);
        }
        #pragma unroll
        for (int it = 0; it < 8; ++it) stg[it] = Vt[tid + NT * it];
        #pragma unroll
        for (int it = 0; it < 8; ++it) {
            int i = tid + NT * it;
            int r = i >> 4, c4 = i & 15;
            u32 off = swz((u32)(r * 128 + c4 * 8));
            u32 h0, lo0, h1, lo1;
            split2(stg[it].x, stg[it].y, h0, lo0);
            split2(stg[it].z, stg[it].w, h1, lo1);
            *(uint2*)(smc + VH_OFF + off) = make_uint2(h0, h1);
            *(uint2*)(smc + VL_OFF + off) = make_uint2(lo0, lo1);
        }
        __syncthreads();

        // ---- S = Q K^T (warp rows 16w..16w+15, all 128 cols) ----
        float s[16][4];
        #pragma unroll
        for (int n = 0; n < 16; ++n)
            #pragma unroll
            for (int c = 0; c < 4; ++c) s[n][c] = 0.0f;

        #pragma unroll
        for (int k4 = 0; k4 < 4; ++k4) {
            u32 qoff = swz(aRB + (u32)k4 * 32 + aKH);
            u32 ah0, ah1, ah2, ah3, al0, al1, al2, al3;
            ldsm4(ah0, ah1, ah2, ah3, sb + QH_OFF + qoff);
            ldsm4(al0, al1, al2, al3, sb + QL_OFF + qoff);
            #pragma unroll
            for (int np = 0; np < 8; ++np) {
                u32 boff = swz((u32)(16 * np + bRow) * 128 + (u32)k4 * 32 + bKH);
                u32 bh0, bh1, bh2, bh3, bl0, bl1, bl2, bl3;
                ldsm4(bh0, bh1, bh2, bh3, sb + KH_OFF + boff);
                ldsm4(bl0, bl1, bl2, bl3, sb + KL_OFF + boff);
                mma_bf16(s[2 * np],     ah0, ah1, ah2, ah3, bh0, bh1);
                mma_bf16(s[2 * np + 1], ah0, ah1, ah2, ah3, bh2, bh3);
                mma_bf16(s[2 * np],     al0, al1, al2, al3, bh0, bh1);
                mma_bf16(s[2 * np + 1], al0, al1, al2, al3, bh2, bh3);
                mma_bf16(s[2 * np],     ah0, ah1, ah2, ah3, bl0, bl1);
                mma_bf16(s[2 * np + 1], ah0, ah1, ah2, ah3, bl2, bl3);
            }
        }

        // ---- mask + scale + online softmax (fragment-native) ----
        const int cb = kt * 128 + 2 * tig;
        float mx0 = -1e30f, mx1 = -1e30f;
        #pragma unroll
        for (int n = 0; n < 16; ++n) {
            int2 ma = *(const int2*)(M0 + cb + 8 * n);
            int2 mb = *(const int2*)(M1 + cb + 8 * n);
            s[n][0] = ma.x ? s[n][0] * 0.125f : -32768.0f;
            s[n][1] = ma.y ? s[n][1] * 0.125f : -32768.0f;
            s[n][2] = mb.x ? s[n][2] * 0.125f : -32768.0f;
            s[n][3] = mb.y ? s[n][3] * 0.125f : -32768.0f;
            mx0 = fmaxf(mx0, fmaxf(s[n][0], s[n][1]));
            mx1 = fmaxf(mx1, fmaxf(s[n][2], s[n][3]));
        }
        mx0 = fmaxf(mx0, __shfl_xor_sync(0xffffffffu, mx0, 1));
        mx0 = fmaxf(mx0, __shfl_xor_sync(0xffffffffu, mx0, 2));
        mx1 = fmaxf(mx1, __shfl_xor_sync(0xffffffffu, mx1, 1));
        mx1 = fmaxf(mx1, __shfl_xor_sync(0xffffffffu, mx1, 2));

        float mn0 = fmaxf(m0, mx0), mn1 = fmaxf(m1, mx1);
        float alpha0 = exp2p((m0 - mn0) * LOG2E);
        float alpha1 = exp2p((m1 - mn1) * LOG2E);
        m0 = mn0; m1 = mn1;

        float sum0 = 0.0f, sum1 = 0.0f;
        #pragma unroll
        for (int n = 0; n < 16; ++n) {
            float p0 = exp2p((s[n][0] - mn0) * LOG2E);
            float p1 = exp2p((s[n][1] - mn0) * LOG2E);
            float p2 = exp2p((s[n][2] - mn1) * LOG2E);
            float p3 = exp2p((s[n][3] - mn1) * LOG2E);
            s[n][0] = p0; s[n][1] = p1; s[n][2] = p2; s[n][3] = p3;
            sum0 += p0 + p1; sum1 += p2 + p3;
        }
        sum0 += __shfl_xor_sync(0xffffffffu, sum0, 1);
        sum0 += __shfl_xor_sync(0xffffffffu, sum0, 2);
        sum1 += __shfl_xor_sync(0xffffffffu, sum1, 1);
        sum1 += __shfl_xor_sync(0xffffffffu, sum1, 2);
        l0 = l0 * alpha0 + sum0;
        l1 = l1 * alpha1 + sum1;

        #pragma unroll
        for (int n = 0; n < 8; ++n) {
            O[n][0] *= alpha0; O[n][1] *= alpha0;
            O[n][2] *= alpha1; O[n][3] *= alpha1;
        }

        // ---- O += P V (P split in regs, V from smem via ldmatrix.trans) ----
        #pragma unroll
        for (int kk = 0; kk < 8; ++kk) {
            u32 ah0 = packbf2(s[2 * kk][0],     s[2 * kk][1]);
            u32 ah1 = packbf2(s[2 * kk][2],     s[2 * kk][3]);
            u32 ah2 = packbf2(s[2 * kk + 1][0], s[2 * kk + 1][1]);
            u32 ah3 = packbf2(s[2 * kk + 1][2], s[2 * kk + 1][3]);
            u32 al0 = packbf2(s[2 * kk][0] - bf_lo(ah0),     s[2 * kk][1] - bf_hi(ah0));
            u32 al1 = packbf2(s[2 * kk][2] - bf_lo(ah1),     s[2 * kk][3] - bf_hi(ah1));
            u32 al2 = packbf2(s[2 * kk + 1][0] - bf_lo(ah2), s[2 * kk + 1][1] - bf_hi(ah2));
            u32 al3 = packbf2(s[2 * kk + 1][2] - bf_lo(ah3), s[2 * kk + 1][3] - bf_hi(ah3));
            u32 vro = (u32)(16 * kk + vRow) * 128;
            #pragma unroll
            for (int np = 0; np < 4; ++np) {
                u32 voff = swz(vro + (u32)np * 32 + vDB);
                u32 vh0, vh1, vh2, vh3, vl0, vl1, vl2, vl3;
                ldsm4t(vh0, vh1, vh2, vh3, sb + VH_OFF + voff);
                ldsm4t(vl0, vl1, vl2, vl3, sb + VL_OFF + voff);
                mma_bf16(O[2 * np],     ah0, ah1, ah2, ah3, vh0, vh1);
                mma_bf16(O[2 * np + 1], ah0, ah1, ah2, ah3, vh2, vh3);
                mma_bf16(O[2 * np],     al0, al1, al2, al3, vh0, vh1);
                mma_bf16(O[2 * np + 1], al0, al1, al2, al3, vh2, vh3);
                mma_bf16(O[2 * np],     ah0, ah1, ah2, ah3, vl0, vl1);
                mma_bf16(O[2 * np + 1], ah0, ah1, ah2, ah3, vl2, vl3);
            }
        }
    }

    // ---- epilogue ----
    float inv0 = 1.0f / l0, inv1 = 1.0f / l1;
    float* o0 = Og + (size_t)row0 * 64 + 2 * tig;
    float* o1 = Og + (size_t)row1 * 64 + 2 * tig;
    #pragma unroll
    for (int n = 0; n < 8; ++n) {
        *(float2*)(o0 + 8 * n) = make_float2(O[n][0] * inv0, O[n][1] * inv0);
        *(float2*)(o1 + 8 * n) = make_float2(O[n][2] * inv1, O[n][3] * inv1);
    }
}

extern "C" void kernel_launch(void* const* d_in, const int* in_sizes, int n_in,
                              void* d_out, int out_size)
{
    const float* Q    = (const float*)d_in[0];
    const float* K    = (const float*)d_in[1];
    const float* V    = (const float*)d_in[2];
    const int*   mask = (const int*)d_in[3];
    float* out = (float*)d_out;

    cudaFuncSetAttribute(attn_mma, cudaFuncAttributeMaxDynamicSharedMemorySize, SMEM_BYTES);
    dim3 grid(Sc / 128, 32);
    attn_mma<<<grid, NT, SMEM_BYTES>>>(Q, K, V, mask, out);
}